// round 8
// baseline (speedup 1.0000x reference)
#include <cuda_runtime.h>
#include <cuda_bf16.h>

#define N_NODES 50000
#define N_EDGES 800000
#define IN_DIM  128
#define OUT_DIM 64

#define BM 64
#define GEMM_BLOCKS ((N_NODES + BM - 1) / BM)      // 782
#define PERM_THREADS (N_EDGES / 4)                 // 200000
#define PERM_BLOCKS ((PERM_THREADS + 255) / 256)   // 782
#define PAD 96                                     // max row degree bin

#define XS_STRIDE 132                              // floats; 528B rows, 16B-aligned
#define SMEM_BYTES (BM * XS_STRIDE * 4 + IN_DIM * OUT_DIM * 4)  // 33792+32768=66560

// ---- device-global scratch (zero-initialized at module load) ---------------
__device__ __align__(16) float g_xw[N_NODES * OUT_DIM];     // x @ W (12.8 MB)
__device__ __align__(16) int   g_cnt[N_NODES];              // per-row fill count
__device__ __align__(16) int2  g_edge[N_NODES * PAD];       // padded bins (38.4 MB)

// ---- packed fp32x2 helpers --------------------------------------------------
__device__ __forceinline__ void ffma2(unsigned long long& d,
                                      unsigned long long a,
                                      unsigned long long b) {
    asm("fma.rn.f32x2 %0, %1, %2, %0;" : "+l"(d) : "l"(a), "l"(b));
}
__device__ __forceinline__ unsigned long long dup2(float x) {
    unsigned long long r;
    asm("mov.b64 %0, {%1, %1};" : "=l"(r) : "f"(x));
    return r;
}

extern __shared__ unsigned char s_raw[];

// ---------------------------------------------------------------------------
// 1) FUSED: gemm (even blocks) + permute-into-bins (odd blocks).
//    GEMM: 64 rows/block, 256 threads, 4x4 micro-tile, full K staged once:
//      xs[r][k] row-major (no duplication)  33.8 KB
//      ws[k][c] row-major                   32.8 KB
//    Inner loop per 4k: 4 LDS.128 (x, broadcast) + 4 LDS.128 (W) + dup + 32 FFMA2.
//    Crossbar ~12 cyc/warp/4k (half of R6's pre-duplicated layout).
// ---------------------------------------------------------------------------
__global__ void __launch_bounds__(256) fused_gemm_permute_kernel(
        const float* __restrict__ x,    const float* __restrict__ w,
        const int*   __restrict__ arow, const int*   __restrict__ acol,
        const float* __restrict__ aval) {

    if (blockIdx.x & 1) {
        // ---- permute into padded bins: 4 edges/thread
        int t = (blockIdx.x >> 1) * blockDim.x + threadIdx.x;
        if (t >= PERM_THREADS) return;
        int4   r = reinterpret_cast<const int4*>(arow)[t];
        int4   c = reinterpret_cast<const int4*>(acol)[t];
        float4 v = reinterpret_cast<const float4*>(aval)[t];
        int p0 = atomicAdd(&g_cnt[r.x], 1);
        int p1 = atomicAdd(&g_cnt[r.y], 1);
        int p2 = atomicAdd(&g_cnt[r.z], 1);
        int p3 = atomicAdd(&g_cnt[r.w], 1);
        if (p0 < PAD) g_edge[r.x * PAD + p0] = make_int2(c.x, __float_as_int(v.x));
        if (p1 < PAD) g_edge[r.y * PAD + p1] = make_int2(c.y, __float_as_int(v.y));
        if (p2 < PAD) g_edge[r.z * PAD + p2] = make_int2(c.z, __float_as_int(v.z));
        if (p3 < PAD) g_edge[r.w * PAD + p3] = make_int2(c.w, __float_as_int(v.w));
        return;
    }

    // ---- gemm
    float* xs = reinterpret_cast<float*>(s_raw);                     // [64][132]
    float* ws = reinterpret_cast<float*>(s_raw + BM * XS_STRIDE * 4); // [128][64]

    const int tid  = threadIdx.x;
    const int tx   = tid & 15;               // cols tx*4 .. +3
    const int ty   = tid >> 4;               // rows ty*4 .. +3
    const int row0 = (blockIdx.x >> 1) * BM;

    const float4* x4 = reinterpret_cast<const float4*>(x);
    const float4* w4 = reinterpret_cast<const float4*>(w);

    // stage W: 2048 float4, coalesced LDG + conflict-free STS.128
    for (int i = tid; i < 2048; i += 256)
        reinterpret_cast<float4*>(ws)[i] = w4[i];
    // stage x row-major: 64 rows x 32 float4
    for (int i = tid; i < 2048; i += 256) {
        int r = i >> 5, kq = i & 31;
        int gr = min(row0 + r, N_NODES - 1);
        *reinterpret_cast<float4*>(&xs[r * XS_STRIDE + kq * 4]) =
            x4[(size_t)gr * 32 + kq];
    }
    __syncthreads();

    unsigned long long acc[4][2];
#pragma unroll
    for (int r = 0; r < 4; r++) { acc[r][0] = 0ull; acc[r][1] = 0ull; }

    const float* xr0 = &xs[(ty * 4 + 0) * XS_STRIDE];
    const float* xr1 = &xs[(ty * 4 + 1) * XS_STRIDE];
    const float* xr2 = &xs[(ty * 4 + 2) * XS_STRIDE];
    const float* xr3 = &xs[(ty * 4 + 3) * XS_STRIDE];

#pragma unroll 8
    for (int kb = 0; kb < IN_DIM; kb += 4) {
        float4 xa0 = *reinterpret_cast<const float4*>(&xr0[kb]);
        float4 xa1 = *reinterpret_cast<const float4*>(&xr1[kb]);
        float4 xa2 = *reinterpret_cast<const float4*>(&xr2[kb]);
        float4 xa3 = *reinterpret_cast<const float4*>(&xr3[kb]);
#pragma unroll
        for (int kk = 0; kk < 4; kk++) {
            ulonglong2 wp = *reinterpret_cast<const ulonglong2*>(
                &ws[(kb + kk) * 64 + tx * 4]);
            unsigned long long a0, a1, a2, a3;
            if      (kk == 0) { a0 = dup2(xa0.x); a1 = dup2(xa1.x); a2 = dup2(xa2.x); a3 = dup2(xa3.x); }
            else if (kk == 1) { a0 = dup2(xa0.y); a1 = dup2(xa1.y); a2 = dup2(xa2.y); a3 = dup2(xa3.y); }
            else if (kk == 2) { a0 = dup2(xa0.z); a1 = dup2(xa1.z); a2 = dup2(xa2.z); a3 = dup2(xa3.z); }
            else              { a0 = dup2(xa0.w); a1 = dup2(xa1.w); a2 = dup2(xa2.w); a3 = dup2(xa3.w); }
            ffma2(acc[0][0], a0, wp.x); ffma2(acc[0][1], a0, wp.y);
            ffma2(acc[1][0], a1, wp.x); ffma2(acc[1][1], a1, wp.y);
            ffma2(acc[2][0], a2, wp.x); ffma2(acc[2][1], a2, wp.y);
            ffma2(acc[3][0], a3, wp.x); ffma2(acc[3][1], a3, wp.y);
        }
    }

#pragma unroll
    for (int r = 0; r < 4; r++) {
        int row = row0 + ty * 4 + r;
        if (row < N_NODES) {
            ulonglong2 o;
            o.x = acc[r][0];
            o.y = acc[r][1];
            *reinterpret_cast<ulonglong2*>(&g_xw[(size_t)row * OUT_DIM + tx * 4]) = o;
        }
    }
}

// ---------------------------------------------------------------------------
// 2) gather + ReLU, warp per row over padded bins.  Per 16-edge chunk all 16
//    xw loads are hoisted (predicated, zero-initialized) before any FMA:
//    MLP=16, one L2-latency exposure per chunk.  Resets g_cnt for next launch.
// ---------------------------------------------------------------------------
__global__ void __launch_bounds__(256) gather_kernel(float2* __restrict__ out2) {
    const int warp_g = (blockIdx.x * blockDim.x + threadIdx.x) >> 5;
    const int lane   = threadIdx.x & 31;
    if (warp_g >= N_NODES) return;

    const int cnt = min(g_cnt[warp_g], PAD);
    if (lane == 0) g_cnt[warp_g] = 0;   // reset for next launch

    const int2* bin = &g_edge[warp_g * PAD];
    const float2* xw2 = reinterpret_cast<const float2*>(g_xw);

    float acc0 = 0.f, acc1 = 0.f;
    for (int base = 0; base < cnt; base += 32) {
        int idx = base + lane;
        int2 e = (idx < cnt) ? bin[idx] : make_int2(0, 0);
        int rem = cnt - base;                       // > 0

        // ---- half A: edges base .. base+15
        {
            float2 m[16];
            float  v[16];
#pragma unroll
            for (int j = 0; j < 16; j++) {
                int c = __shfl_sync(0xffffffffu, e.x, j);
                v[j]  = __int_as_float(__shfl_sync(0xffffffffu, e.y, j));
                m[j]  = make_float2(0.f, 0.f);
                if (j < rem) m[j] = __ldg(&xw2[(size_t)c * 32 + lane]);
            }
#pragma unroll
            for (int j = 0; j < 16; j++) {
                acc0 = fmaf(v[j], m[j].x, acc0);
                acc1 = fmaf(v[j], m[j].y, acc1);
            }
        }
        // ---- half B: edges base+16 .. base+31 (skip if row done)
        if (rem > 16) {
            float2 m[16];
            float  v[16];
#pragma unroll
            for (int j = 0; j < 16; j++) {
                int c = __shfl_sync(0xffffffffu, e.x, j + 16);
                v[j]  = __int_as_float(__shfl_sync(0xffffffffu, e.y, j + 16));
                m[j]  = make_float2(0.f, 0.f);
                if (j + 16 < rem) m[j] = __ldg(&xw2[(size_t)c * 32 + lane]);
            }
#pragma unroll
            for (int j = 0; j < 16; j++) {
                acc0 = fmaf(v[j], m[j].x, acc0);
                acc1 = fmaf(v[j], m[j].y, acc1);
            }
        }
    }
    out2[(size_t)warp_g * 32 + lane] =
        make_float2(fmaxf(acc0, 0.f), fmaxf(acc1, 0.f));
}

extern "C" void kernel_launch(void* const* d_in, const int* in_sizes, int n_in,
                              void* d_out, int out_size) {
    const float* x    = (const float*)d_in[0];
    const float* w    = (const float*)d_in[1];
    const int*   arow = (const int*)  d_in[2];
    const int*   acol = (const int*)  d_in[3];
    const float* aval = (const float*)d_in[4];
    float2* out2 = (float2*)d_out;

    cudaFuncSetAttribute(fused_gemm_permute_kernel,
                         cudaFuncAttributeMaxDynamicSharedMemorySize, SMEM_BYTES);

    fused_gemm_permute_kernel<<<GEMM_BLOCKS + PERM_BLOCKS, 256, SMEM_BYTES>>>(
        x, w, arow, acol, aval);
    gather_kernel<<<(N_NODES * 32 + 255) / 256, 256>>>(out2);
}

// round 9
// speedup vs baseline: 1.3503x; 1.3503x over previous
#include <cuda_runtime.h>
#include <cuda_fp16.h>

#define N_NODES 50000
#define N_EDGES 800000
#define IN_DIM  128
#define OUT_DIM 64

#define BM 64
#define GEMM_BLOCKS ((N_NODES + BM - 1) / BM)      // 782
#define PERM_THREADS (N_EDGES / 4)                 // 200000
#define PERM_BLOCKS ((PERM_THREADS + 255) / 256)   // 782
#define PAD 96                                     // max row degree bin

#define XS_STRIDE 132                              // floats; 528B rows, 16B-aligned
#define SMEM_BYTES (BM * XS_STRIDE * 4 + IN_DIM * OUT_DIM * 4)  // 66560

// ---- device-global scratch (zero-initialized at module load) ---------------
__device__ __align__(16) __half g_xw[N_NODES * OUT_DIM];    // x @ W, fp16 (6.4 MB)
__device__ __align__(16) int    g_cnt[N_NODES];             // per-row fill count
__device__ __align__(16) int2   g_edge[N_NODES * PAD];      // padded bins (38.4 MB)

// ---- packed fp32x2 helpers --------------------------------------------------
__device__ __forceinline__ void ffma2(unsigned long long& d,
                                      unsigned long long a,
                                      unsigned long long b) {
    asm("fma.rn.f32x2 %0, %1, %2, %0;" : "+l"(d) : "l"(a), "l"(b));
}
__device__ __forceinline__ unsigned long long dup2(float x) {
    unsigned long long r;
    asm("mov.b64 %0, {%1, %1};" : "=l"(r) : "f"(x));
    return r;
}
__device__ __forceinline__ float2 unpack2(unsigned long long p) {
    float lo, hi;
    asm("mov.b64 {%0, %1}, %2;" : "=f"(lo), "=f"(hi) : "l"(p));
    return make_float2(lo, hi);
}

extern __shared__ unsigned char s_raw[];

// ---------------------------------------------------------------------------
// 1) FUSED: gemm (even blocks) + permute-into-bins (odd blocks).
//    GEMM: 64 rows/block, 256 threads, 4x4 micro-tile, full K staged once;
//    x staged row-major (LDS.128 broadcast), W row-major; f32x2 FFMA;
//    epilogue converts to half2 and stores g_xw in fp16.
// ---------------------------------------------------------------------------
__global__ void __launch_bounds__(256) fused_gemm_permute_kernel(
        const float* __restrict__ x,    const float* __restrict__ w,
        const int*   __restrict__ arow, const int*   __restrict__ acol,
        const float* __restrict__ aval) {

    if (blockIdx.x & 1) {
        // ---- permute into padded bins: 4 edges/thread
        int t = (blockIdx.x >> 1) * blockDim.x + threadIdx.x;
        if (t >= PERM_THREADS) return;
        int4   r = reinterpret_cast<const int4*>(arow)[t];
        int4   c = reinterpret_cast<const int4*>(acol)[t];
        float4 v = reinterpret_cast<const float4*>(aval)[t];
        int p0 = atomicAdd(&g_cnt[r.x], 1);
        int p1 = atomicAdd(&g_cnt[r.y], 1);
        int p2 = atomicAdd(&g_cnt[r.z], 1);
        int p3 = atomicAdd(&g_cnt[r.w], 1);
        if (p0 < PAD) g_edge[r.x * PAD + p0] = make_int2(c.x, __float_as_int(v.x));
        if (p1 < PAD) g_edge[r.y * PAD + p1] = make_int2(c.y, __float_as_int(v.y));
        if (p2 < PAD) g_edge[r.z * PAD + p2] = make_int2(c.z, __float_as_int(v.z));
        if (p3 < PAD) g_edge[r.w * PAD + p3] = make_int2(c.w, __float_as_int(v.w));
        return;
    }

    // ---- gemm
    float* xs = reinterpret_cast<float*>(s_raw);                      // [64][132]
    float* ws = reinterpret_cast<float*>(s_raw + BM * XS_STRIDE * 4); // [128][64]

    const int tid  = threadIdx.x;
    const int tx   = tid & 15;               // cols tx*4 .. +3
    const int ty   = tid >> 4;               // rows ty*4 .. +3
    const int row0 = (blockIdx.x >> 1) * BM;

    const float4* x4 = reinterpret_cast<const float4*>(x);
    const float4* w4 = reinterpret_cast<const float4*>(w);

    for (int i = tid; i < 2048; i += 256)
        reinterpret_cast<float4*>(ws)[i] = w4[i];
    for (int i = tid; i < 2048; i += 256) {
        int r = i >> 5, kq = i & 31;
        int gr = min(row0 + r, N_NODES - 1);
        *reinterpret_cast<float4*>(&xs[r * XS_STRIDE + kq * 4]) =
            x4[(size_t)gr * 32 + kq];
    }
    __syncthreads();

    unsigned long long acc[4][2];
#pragma unroll
    for (int r = 0; r < 4; r++) { acc[r][0] = 0ull; acc[r][1] = 0ull; }

    const float* xr0 = &xs[(ty * 4 + 0) * XS_STRIDE];
    const float* xr1 = &xs[(ty * 4 + 1) * XS_STRIDE];
    const float* xr2 = &xs[(ty * 4 + 2) * XS_STRIDE];
    const float* xr3 = &xs[(ty * 4 + 3) * XS_STRIDE];

#pragma unroll 8
    for (int kb = 0; kb < IN_DIM; kb += 4) {
        float4 xa0 = *reinterpret_cast<const float4*>(&xr0[kb]);
        float4 xa1 = *reinterpret_cast<const float4*>(&xr1[kb]);
        float4 xa2 = *reinterpret_cast<const float4*>(&xr2[kb]);
        float4 xa3 = *reinterpret_cast<const float4*>(&xr3[kb]);
#pragma unroll
        for (int kk = 0; kk < 4; kk++) {
            ulonglong2 wp = *reinterpret_cast<const ulonglong2*>(
                &ws[(kb + kk) * 64 + tx * 4]);
            unsigned long long a0, a1, a2, a3;
            if      (kk == 0) { a0 = dup2(xa0.x); a1 = dup2(xa1.x); a2 = dup2(xa2.x); a3 = dup2(xa3.x); }
            else if (kk == 1) { a0 = dup2(xa0.y); a1 = dup2(xa1.y); a2 = dup2(xa2.y); a3 = dup2(xa3.y); }
            else if (kk == 2) { a0 = dup2(xa0.z); a1 = dup2(xa1.z); a2 = dup2(xa2.z); a3 = dup2(xa3.z); }
            else              { a0 = dup2(xa0.w); a1 = dup2(xa1.w); a2 = dup2(xa2.w); a3 = dup2(xa3.w); }
            ffma2(acc[0][0], a0, wp.x); ffma2(acc[0][1], a0, wp.y);
            ffma2(acc[1][0], a1, wp.x); ffma2(acc[1][1], a1, wp.y);
            ffma2(acc[2][0], a2, wp.x); ffma2(acc[2][1], a2, wp.y);
            ffma2(acc[3][0], a3, wp.x); ffma2(acc[3][1], a3, wp.y);
        }
    }

    // epilogue: f32x2 -> half2, store 8B per row-slice
#pragma unroll
    for (int r = 0; r < 4; r++) {
        int row = row0 + ty * 4 + r;
        if (row < N_NODES) {
            float2 f0 = unpack2(acc[r][0]);   // cols tx*4, tx*4+1
            float2 f1 = unpack2(acc[r][1]);   // cols tx*4+2, tx*4+3
            __half2 h0 = __floats2half2_rn(f0.x, f0.y);
            __half2 h1 = __floats2half2_rn(f1.x, f1.y);
            uint2 o;
            o.x = *reinterpret_cast<unsigned int*>(&h0);
            o.y = *reinterpret_cast<unsigned int*>(&h1);
            *reinterpret_cast<uint2*>(&g_xw[(size_t)row * OUT_DIM + tx * 4]) = o;
        }
    }
}

// ---------------------------------------------------------------------------
// 2) gather + ReLU, warp per row over padded bins (R6 structure: simple
//    unroll-4 loop, low regs, high occupancy).  half2 xw loads: 128B/warp/edge.
//    Resets g_cnt for the next launch.
// ---------------------------------------------------------------------------
__global__ void __launch_bounds__(256) gather_kernel(float2* __restrict__ out2) {
    const int warp_g = (blockIdx.x * blockDim.x + threadIdx.x) >> 5;
    const int lane   = threadIdx.x & 31;
    if (warp_g >= N_NODES) return;

    const int cnt = min(g_cnt[warp_g], PAD);
    if (lane == 0) g_cnt[warp_g] = 0;   // reset for next launch

    const int2* bin = &g_edge[warp_g * PAD];
    const __half2* xwh = reinterpret_cast<const __half2*>(g_xw);

    float acc0 = 0.f, acc1 = 0.f;
    for (int base = 0; base < cnt; base += 32) {
        int idx = base + lane;
        int2 e = (idx < cnt) ? bin[idx] : make_int2(0, 0);
        int n = min(32, cnt - base);
#pragma unroll 4
        for (int j = 0; j < n; j++) {
            int   c = __shfl_sync(0xffffffffu, e.x, j);
            float v = __int_as_float(__shfl_sync(0xffffffffu, e.y, j));
            __half2 mh = __ldg(&xwh[(size_t)c * 32 + lane]);
            float2 m = __half22float2(mh);
            acc0 = fmaf(v, m.x, acc0);
            acc1 = fmaf(v, m.y, acc1);
        }
    }
    out2[(size_t)warp_g * 32 + lane] =
        make_float2(fmaxf(acc0, 0.f), fmaxf(acc1, 0.f));
}

extern "C" void kernel_launch(void* const* d_in, const int* in_sizes, int n_in,
                              void* d_out, int out_size) {
    const float* x    = (const float*)d_in[0];
    const float* w    = (const float*)d_in[1];
    const int*   arow = (const int*)  d_in[2];
    const int*   acol = (const int*)  d_in[3];
    const float* aval = (const float*)d_in[4];
    float2* out2 = (float2*)d_out;

    cudaFuncSetAttribute(fused_gemm_permute_kernel,
                         cudaFuncAttributeMaxDynamicSharedMemorySize, SMEM_BYTES);

    fused_gemm_permute_kernel<<<GEMM_BLOCKS + PERM_BLOCKS, 256, SMEM_BYTES>>>(
        x, w, arow, acol, aval);
    gather_kernel<<<(N_NODES * 32 + 255) / 256, 256>>>(out2);
}

// round 10
// speedup vs baseline: 1.3542x; 1.0029x over previous
#include <cuda_runtime.h>
#include <cuda_fp16.h>

#define N_NODES 50000
#define N_EDGES 800000
#define IN_DIM  128
#define OUT_DIM 64

#define BM 64
#define GEMM_BLOCKS ((N_NODES + BM - 1) / BM)      // 782
#define PERM_THREADS (N_EDGES / 4)                 // 200000
#define PERM_BLOCKS ((PERM_THREADS + 255) / 256)   // 782
#define PAD 96                                     // max row degree bin

// ---- device-global scratch (zero-initialized at module load) ---------------
__device__ __align__(16) __half g_xw[N_NODES * OUT_DIM];    // x @ W, fp16 (6.4 MB)
__device__ __align__(16) int    g_cnt[N_NODES];             // per-row fill count
__device__ __align__(16) int2   g_edge[N_NODES * PAD];      // padded bins (38.4 MB)

// ---- packed fp32x2 helpers --------------------------------------------------
__device__ __forceinline__ void ffma2(unsigned long long& d,
                                      unsigned long long a,
                                      unsigned long long b) {
    asm("fma.rn.f32x2 %0, %1, %2, %0;" : "+l"(d) : "l"(a), "l"(b));
}
__device__ __forceinline__ unsigned long long dup2(float x) {
    unsigned long long r;
    asm("mov.b64 %0, {%1, %1};" : "=l"(r) : "f"(x));
    return r;
}
__device__ __forceinline__ float2 unpack2(unsigned long long p) {
    float lo, hi;
    asm("mov.b64 {%0, %1}, %2;" : "=f"(lo), "=f"(hi) : "l"(p));
    return make_float2(lo, hi);
}

// ---------------------------------------------------------------------------
// 1) FUSED: gemm (even blocks) + permute-into-bins (odd blocks), 1:1
//    interleaved — EXACT R6 structure (the 70us champion's gemm).
//    GEMM: 64 rows/block, 256 threads, 4x4 micro-tile, full K staged once:
//      xsd[r][k]: x pre-duplicated as f32x2  (64 x 130 x 8B = 66.6 KB)
//      ws [k][c]: W row-major                (128 x 64 x 4B = 32.8 KB)
//    Inner loop per k: 4 x LDS.64 (broadcast) + 1 x LDS.128 + 8 x FFMA2.
//    Epilogue converts f32x2 accumulators to half2 (only delta vs R6).
// ---------------------------------------------------------------------------
#define XSD_STRIDE 130
#define SMEM_BYTES (BM * XSD_STRIDE * 8 + IN_DIM * OUT_DIM * 4)   // 99,328
extern __shared__ unsigned char s_raw[];

__global__ void __launch_bounds__(256, 2) fused_gemm_permute_kernel(
        const float* __restrict__ x,    const float* __restrict__ w,
        const int*   __restrict__ arow, const int*   __restrict__ acol,
        const float* __restrict__ aval) {

    if (blockIdx.x & 1) {
        // ---- permute into padded bins: 4 edges/thread
        int t = (blockIdx.x >> 1) * blockDim.x + threadIdx.x;
        if (t >= PERM_THREADS) return;
        int4   r = reinterpret_cast<const int4*>(arow)[t];
        int4   c = reinterpret_cast<const int4*>(acol)[t];
        float4 v = reinterpret_cast<const float4*>(aval)[t];
        int p0 = atomicAdd(&g_cnt[r.x], 1);
        int p1 = atomicAdd(&g_cnt[r.y], 1);
        int p2 = atomicAdd(&g_cnt[r.z], 1);
        int p3 = atomicAdd(&g_cnt[r.w], 1);
        if (p0 < PAD) g_edge[r.x * PAD + p0] = make_int2(c.x, __float_as_int(v.x));
        if (p1 < PAD) g_edge[r.y * PAD + p1] = make_int2(c.y, __float_as_int(v.y));
        if (p2 < PAD) g_edge[r.z * PAD + p2] = make_int2(c.z, __float_as_int(v.z));
        if (p3 < PAD) g_edge[r.w * PAD + p3] = make_int2(c.w, __float_as_int(v.w));
        return;
    }

    // ---- gemm
    unsigned long long* xsd = reinterpret_cast<unsigned long long*>(s_raw);
    float* ws = reinterpret_cast<float*>(s_raw + BM * XSD_STRIDE * 8);

    const int tid  = threadIdx.x;
    const int tx   = tid & 15;             // cols tx*4 .. +3
    const int ty   = tid >> 4;             // rows ty*4 .. +3
    const int row0 = (blockIdx.x >> 1) * BM;

    const float4* x4 = reinterpret_cast<const float4*>(x);
    const float4* w4 = reinterpret_cast<const float4*>(w);

    // stage W: 128x64 floats = 2048 float4
    for (int i = tid; i < 2048; i += 256) {
        int k = i >> 4, cq = i & 15;
        reinterpret_cast<float4*>(&ws[k * 64])[cq] = w4[i];
    }
    // stage x pre-duplicated: 64 rows x 32 float4
    for (int i = tid; i < 2048; i += 256) {
        int r = i >> 5, kq = i & 31;
        int gr = min(row0 + r, N_NODES - 1);
        float4 xv = x4[(size_t)gr * 32 + kq];
        ulonglong2* dst = reinterpret_cast<ulonglong2*>(&xsd[r * XSD_STRIDE + kq * 4]);
        ulonglong2 a, b;
        a.x = dup2(xv.x); a.y = dup2(xv.y);
        b.x = dup2(xv.z); b.y = dup2(xv.w);
        dst[0] = a;
        dst[1] = b;
    }
    __syncthreads();

    unsigned long long acc[4][2];
#pragma unroll
    for (int r = 0; r < 4; r++) { acc[r][0] = 0ull; acc[r][1] = 0ull; }

    const unsigned long long* xr0 = &xsd[(ty * 4 + 0) * XSD_STRIDE];
    const unsigned long long* xr1 = &xsd[(ty * 4 + 1) * XSD_STRIDE];
    const unsigned long long* xr2 = &xsd[(ty * 4 + 2) * XSD_STRIDE];
    const unsigned long long* xr3 = &xsd[(ty * 4 + 3) * XSD_STRIDE];

#pragma unroll 16
    for (int k = 0; k < IN_DIM; k++) {
        ulonglong2 wp = *reinterpret_cast<const ulonglong2*>(&ws[k * 64 + tx * 4]);
        unsigned long long a0 = xr0[k];
        unsigned long long a1 = xr1[k];
        unsigned long long a2 = xr2[k];
        unsigned long long a3 = xr3[k];
        ffma2(acc[0][0], a0, wp.x); ffma2(acc[0][1], a0, wp.y);
        ffma2(acc[1][0], a1, wp.x); ffma2(acc[1][1], a1, wp.y);
        ffma2(acc[2][0], a2, wp.x); ffma2(acc[2][1], a2, wp.y);
        ffma2(acc[3][0], a3, wp.x); ffma2(acc[3][1], a3, wp.y);
    }

    // epilogue: f32x2 -> half2, 8B store per row-slice (only delta vs R6)
#pragma unroll
    for (int r = 0; r < 4; r++) {
        int row = row0 + ty * 4 + r;
        if (row < N_NODES) {
            float2 f0 = unpack2(acc[r][0]);
            float2 f1 = unpack2(acc[r][1]);
            __half2 h0 = __floats2half2_rn(f0.x, f0.y);
            __half2 h1 = __floats2half2_rn(f1.x, f1.y);
            uint2 o;
            o.x = *reinterpret_cast<unsigned int*>(&h0);
            o.y = *reinterpret_cast<unsigned int*>(&h1);
            *reinterpret_cast<uint2*>(&g_xw[(size_t)row * OUT_DIM + tx * 4]) = o;
        }
    }
}

// ---------------------------------------------------------------------------
// 2) gather + ReLU, warp per row over padded bins — EXACT R6 structure
//    (simple unroll-4 loop, low regs, high occupancy), half2 xw loads.
//    Resets g_cnt for the next launch (replaces zero_cnt kernel).
// ---------------------------------------------------------------------------
__global__ void __launch_bounds__(256) gather_kernel(float2* __restrict__ out2) {
    const int warp_g = (blockIdx.x * blockDim.x + threadIdx.x) >> 5;
    const int lane   = threadIdx.x & 31;
    if (warp_g >= N_NODES) return;

    const int cnt = min(g_cnt[warp_g], PAD);
    if (lane == 0) g_cnt[warp_g] = 0;   // reset for next launch

    const int2* bin = &g_edge[warp_g * PAD];
    const __half2* xwh = reinterpret_cast<const __half2*>(g_xw);

    float acc0 = 0.f, acc1 = 0.f;
    for (int base = 0; base < cnt; base += 32) {
        int idx = base + lane;
        int2 e = (idx < cnt) ? bin[idx] : make_int2(0, 0);
        int n = min(32, cnt - base);
#pragma unroll 4
        for (int j = 0; j < n; j++) {
            int   c = __shfl_sync(0xffffffffu, e.x, j);
            float v = __int_as_float(__shfl_sync(0xffffffffu, e.y, j));
            __half2 mh = __ldg(&xwh[(size_t)c * 32 + lane]);
            float2 m = __half22float2(mh);
            acc0 = fmaf(v, m.x, acc0);
            acc1 = fmaf(v, m.y, acc1);
        }
    }
    out2[(size_t)warp_g * 32 + lane] =
        make_float2(fmaxf(acc0, 0.f), fmaxf(acc1, 0.f));
}

extern "C" void kernel_launch(void* const* d_in, const int* in_sizes, int n_in,
                              void* d_out, int out_size) {
    const float* x    = (const float*)d_in[0];
    const float* w    = (const float*)d_in[1];
    const int*   arow = (const int*)  d_in[2];
    const int*   acol = (const int*)  d_in[3];
    const float* aval = (const float*)d_in[4];
    float2* out2 = (float2*)d_out;

    cudaFuncSetAttribute(fused_gemm_permute_kernel,
                         cudaFuncAttributeMaxDynamicSharedMemorySize, SMEM_BYTES);

    fused_gemm_permute_kernel<<<GEMM_BLOCKS + PERM_BLOCKS, 256, SMEM_BYTES>>>(
        x, w, arow, acol, aval);
    gather_kernel<<<(N_NODES * 32 + 255) / 256, 256>>>(out2);
}

// round 11
// speedup vs baseline: 2.1341x; 1.5759x over previous
#include <cuda_runtime.h>
#include <cuda_bf16.h>

#define N_NODES 50000
#define N_EDGES 800000
#define IN_DIM  128
#define OUT_DIM 64

#define BM 64
#define GEMM_BLOCKS ((N_NODES + BM - 1) / BM)      // 782
#define PERM_THREADS (N_EDGES / 4)                 // 200000
#define PERM_BLOCKS ((PERM_THREADS + 255) / 256)   // 782
#define PAD 96                                     // max row degree bin

// ---- device-global scratch -------------------------------------------------
__device__ __align__(16) float g_xw[N_NODES * OUT_DIM];     // x @ W (12.8 MB)
__device__ __align__(16) int   g_cnt[N_NODES];              // per-row fill count
__device__ __align__(16) int2  g_edge[N_NODES * PAD];       // padded bins (38.4 MB)

// ---- packed fp32x2 helpers --------------------------------------------------
__device__ __forceinline__ void ffma2(unsigned long long& d,
                                      unsigned long long a,
                                      unsigned long long b) {
    asm("fma.rn.f32x2 %0, %1, %2, %0;" : "+l"(d) : "l"(a), "l"(b));
}
__device__ __forceinline__ unsigned long long dup2(float x) {
    unsigned long long r;
    asm("mov.b64 %0, {%1, %1};" : "=l"(r) : "f"(x));
    return r;
}

// ---------------------------------------------------------------------------
// 1) zero per-row counters (R6 structure)
// ---------------------------------------------------------------------------
__global__ void __launch_bounds__(256) zero_cnt_kernel() {
    int i = blockIdx.x * blockDim.x + threadIdx.x;
    if (i < N_NODES / 4)
        reinterpret_cast<int4*>(g_cnt)[i] = make_int4(0, 0, 0, 0);
}

// ---------------------------------------------------------------------------
// 2) FUSED: gemm (even blocks) + permute-into-bins (odd blocks) — EXACT R6.
// ---------------------------------------------------------------------------
#define XSD_STRIDE 130
#define SMEM_BYTES (BM * XSD_STRIDE * 8 + IN_DIM * OUT_DIM * 4)   // 99,328
extern __shared__ unsigned char s_raw[];

__global__ void __launch_bounds__(256, 2) fused_gemm_permute_kernel(
        const float* __restrict__ x,    const float* __restrict__ w,
        const int*   __restrict__ arow, const int*   __restrict__ acol,
        const float* __restrict__ aval) {

    if (blockIdx.x & 1) {
        // ---- permute into padded bins: 4 edges/thread
        int t = (blockIdx.x >> 1) * blockDim.x + threadIdx.x;
        if (t >= PERM_THREADS) return;
        int4   r = reinterpret_cast<const int4*>(arow)[t];
        int4   c = reinterpret_cast<const int4*>(acol)[t];
        float4 v = reinterpret_cast<const float4*>(aval)[t];
        int p0 = atomicAdd(&g_cnt[r.x], 1);
        int p1 = atomicAdd(&g_cnt[r.y], 1);
        int p2 = atomicAdd(&g_cnt[r.z], 1);
        int p3 = atomicAdd(&g_cnt[r.w], 1);
        if (p0 < PAD) g_edge[r.x * PAD + p0] = make_int2(c.x, __float_as_int(v.x));
        if (p1 < PAD) g_edge[r.y * PAD + p1] = make_int2(c.y, __float_as_int(v.y));
        if (p2 < PAD) g_edge[r.z * PAD + p2] = make_int2(c.z, __float_as_int(v.z));
        if (p3 < PAD) g_edge[r.w * PAD + p3] = make_int2(c.w, __float_as_int(v.w));
        return;
    }

    // ---- gemm
    unsigned long long* xsd = reinterpret_cast<unsigned long long*>(s_raw);
    float* ws = reinterpret_cast<float*>(s_raw + BM * XSD_STRIDE * 8);

    const int tid  = threadIdx.x;
    const int tx   = tid & 15;             // cols tx*4 .. +3
    const int ty   = tid >> 4;             // rows ty*4 .. +3
    const int row0 = (blockIdx.x >> 1) * BM;

    const float4* x4 = reinterpret_cast<const float4*>(x);
    const float4* w4 = reinterpret_cast<const float4*>(w);

    // stage W: 128x64 floats = 2048 float4
    for (int i = tid; i < 2048; i += 256) {
        int k = i >> 4, cq = i & 15;
        reinterpret_cast<float4*>(&ws[k * 64])[cq] = w4[i];
    }
    // stage x pre-duplicated: 64 rows x 32 float4
    for (int i = tid; i < 2048; i += 256) {
        int r = i >> 5, kq = i & 31;
        int gr = min(row0 + r, N_NODES - 1);
        float4 xv = x4[(size_t)gr * 32 + kq];
        ulonglong2* dst = reinterpret_cast<ulonglong2*>(&xsd[r * XSD_STRIDE + kq * 4]);
        ulonglong2 a, b;
        a.x = dup2(xv.x); a.y = dup2(xv.y);
        b.x = dup2(xv.z); b.y = dup2(xv.w);
        dst[0] = a;
        dst[1] = b;
    }
    __syncthreads();

    unsigned long long acc[4][2];
#pragma unroll
    for (int r = 0; r < 4; r++) { acc[r][0] = 0ull; acc[r][1] = 0ull; }

    const unsigned long long* xr0 = &xsd[(ty * 4 + 0) * XSD_STRIDE];
    const unsigned long long* xr1 = &xsd[(ty * 4 + 1) * XSD_STRIDE];
    const unsigned long long* xr2 = &xsd[(ty * 4 + 2) * XSD_STRIDE];
    const unsigned long long* xr3 = &xsd[(ty * 4 + 3) * XSD_STRIDE];

#pragma unroll 16
    for (int k = 0; k < IN_DIM; k++) {
        ulonglong2 wp = *reinterpret_cast<const ulonglong2*>(&ws[k * 64 + tx * 4]);
        unsigned long long a0 = xr0[k];
        unsigned long long a1 = xr1[k];
        unsigned long long a2 = xr2[k];
        unsigned long long a3 = xr3[k];
        ffma2(acc[0][0], a0, wp.x); ffma2(acc[0][1], a0, wp.y);
        ffma2(acc[1][0], a1, wp.x); ffma2(acc[1][1], a1, wp.y);
        ffma2(acc[2][0], a2, wp.x); ffma2(acc[2][1], a2, wp.y);
        ffma2(acc[3][0], a3, wp.x); ffma2(acc[3][1], a3, wp.y);
    }

#pragma unroll
    for (int r = 0; r < 4; r++) {
        int row = row0 + ty * 4 + r;
        if (row < N_NODES) {
            ulonglong2 o;
            o.x = acc[r][0];
            o.y = acc[r][1];
            *reinterpret_cast<ulonglong2*>(&g_xw[(size_t)row * OUT_DIM + tx * 4]) = o;
        }
    }
}

// ---------------------------------------------------------------------------
// 3) gather + ReLU, warp per row over padded bins — R6 structure, with the
//    single delta: unroll 8 (MLP 4 -> 8 on the SHFL->LDG->FMA chain).
//    No g_cnt reset here (zero_cnt kernel owns it, as in R6).
// ---------------------------------------------------------------------------
__global__ void __launch_bounds__(256) gather_kernel(float2* __restrict__ out2) {
    const int warp_g = (blockIdx.x * blockDim.x + threadIdx.x) >> 5;
    const int lane   = threadIdx.x & 31;
    if (warp_g >= N_NODES) return;

    const int cnt = min(g_cnt[warp_g], PAD);
    const int2* bin = &g_edge[warp_g * PAD];
    const float2* xw2 = reinterpret_cast<const float2*>(g_xw);

    float acc0 = 0.f, acc1 = 0.f;
    for (int base = 0; base < cnt; base += 32) {
        int idx = base + lane;
        int2 e = (idx < cnt) ? bin[idx] : make_int2(0, 0);
        int n = min(32, cnt - base);
#pragma unroll 8
        for (int j = 0; j < n; j++) {
            int   c = __shfl_sync(0xffffffffu, e.x, j);
            float v = __int_as_float(__shfl_sync(0xffffffffu, e.y, j));
            float2 m = __ldg(&xw2[(size_t)c * 32 + lane]);
            acc0 = fmaf(v, m.x, acc0);
            acc1 = fmaf(v, m.y, acc1);
        }
    }
    out2[(size_t)warp_g * 32 + lane] =
        make_float2(fmaxf(acc0, 0.f), fmaxf(acc1, 0.f));
}

extern "C" void kernel_launch(void* const* d_in, const int* in_sizes, int n_in,
                              void* d_out, int out_size) {
    const float* x    = (const float*)d_in[0];
    const float* w    = (const float*)d_in[1];
    const int*   arow = (const int*)  d_in[2];
    const int*   acol = (const int*)  d_in[3];
    const float* aval = (const float*)d_in[4];
    float2* out2 = (float2*)d_out;

    cudaFuncSetAttribute(fused_gemm_permute_kernel,
                         cudaFuncAttributeMaxDynamicSharedMemorySize, SMEM_BYTES);

    zero_cnt_kernel<<<(N_NODES / 4 + 255) / 256, 256>>>();
    fused_gemm_permute_kernel<<<GEMM_BLOCKS + PERM_BLOCKS, 256, SMEM_BYTES>>>(
        x, w, arow, acol, aval);
    gather_kernel<<<(N_NODES * 32 + 255) / 256, 256>>>(out2);
}